// round 8
// baseline (speedup 1.0000x reference)
#include <cuda_runtime.h>

#define VOCAB 32
#define UTT_LEN 16
#define NTYPES 5
#define MPT 10
#define SUPPORT 100000
#define BATCH 2048

#define NS 32                            // support chunks (finer: smooth waves)
#define CHUNK (SUPPORT / NS)             // 3125
#define TPB 256
#define FULL_ITERS (CHUNK / TPB)         // 12
#define TAIL (CHUNK - FULL_ITERS * TPB)  // 53
#define NGROUPS (BATCH / 32)             // 64

#define ENTRIES (SUPPORT * UTT_LEN)      // 1,600,000 (divisible by 32)

// scratch (no cudaMalloc allowed)
__device__ unsigned char g_packed[ENTRIES];           // token*4 per position
__device__ unsigned int  g_keys[BATCH];               // (cnt<<17)|(131071-row)
__device__ int g_u64, g_m64;                          // dtype flags

// ---------------------------------------------------------------------------
// Kernel 1 (fused): detect int width + zero keys + decode one-hot support.
// R3-exact (33.8us, DRAM 78% ~ LTS structural ceiling). Warp-cooperative,
// fully coalesced: each warp owns 32 entries = 4KB contiguous.
// ---------------------------------------------------------------------------
__global__ void __launch_bounds__(256) decode_kernel(
        const float* __restrict__ support,
        const int* __restrict__ utts32,
        const int* __restrict__ mean32) {
    const unsigned tid  = blockIdx.x * blockDim.x + threadIdx.x;
    const unsigned lane = threadIdx.x & 31;

    // fused dtype detection (first warp). Values are small non-negative ints;
    // if int64 (LE), every odd 32-bit word of the first 128 pairs is 0.
    if (tid < 32) {
        bool unz = false, mnz = false;
        for (int i = (int)tid; i < 128; i += 32) {
            unz |= (utts32[2 * i + 1] != 0);
            mnz |= (mean32[2 * i + 1] != 0);
        }
        unsigned ub = __ballot_sync(0xffffffffu, unz);
        unsigned mb = __ballot_sync(0xffffffffu, mnz);
        if (tid == 0) { g_u64 = (ub == 0); g_m64 = (mb == 0); }
    }
    if (tid < BATCH) g_keys[tid] = 0u;

    const unsigned gwarp = tid >> 5;              // global warp id
    const unsigned base  = gwarp * 32;            // first entry of this warp
    if (base >= ENTRIES) return;

    const float4* p = reinterpret_cast<const float4*>(support) + (size_t)base * 8;
    const int myr = (int)(lane >> 2);             // round holding my entry
    const int sh  = (int)(lane & 3) * 8;          // byte of my entry in ballots

    unsigned mysub = 0;
#pragma unroll
    for (int r = 0; r < 8; r++) {
        float4 v = __ldcs(p + r * 32 + lane);     // 512B contiguous, streaming
        unsigned bx = __ballot_sync(0xffffffffu, v.x != 0.0f);
        unsigned by = __ballot_sync(0xffffffffu, v.y != 0.0f);
        unsigned bz = __ballot_sync(0xffffffffu, v.z != 0.0f);
        unsigned bw = __ballot_sync(0xffffffffu, v.w != 0.0f);
        unsigned sub = ((bx >> sh) & 0xFFu)
                     | (((by >> sh) & 0xFFu) << 8)
                     | (((bz >> sh) & 0xFFu) << 16)
                     | (((bw >> sh) & 0xFFu) << 24);
        if (r == myr) mysub = sub;
    }
    int b = __ffs(mysub) - 1;                     // bit index in submask
    int v = ((b & 7) << 2) | (b >> 3);            // vocab token
    g_packed[base + lane] = (unsigned char)(v << 2);  // pre-scaled x4
}

// ---------------------------------------------------------------------------
// Kernel 2: bit-sliced match counting + argmax. R3 body; NS=32 so blocks are
// half-size (5.3us): grid 2048 vs chip capacity ~740 -> 2.77 waves, tail idle
// shrinks ~2x. Local row now 12 bits (tid:8 | iter:4) -> one fewer plane.
// ---------------------------------------------------------------------------
__device__ __forceinline__ void fa(unsigned a, unsigned b, unsigned c,
                                   unsigned& s, unsigned& cy) {
    s  = a ^ b ^ c;                       // LOP3 0x96
    cy = (a & b) | (a & c) | (b & c);     // LOP3 0xE8
}
__device__ __forceinline__ void ha(unsigned a, unsigned b,
                                   unsigned& s, unsigned& cy) {
    s = a ^ b; cy = a & b;
}

__global__ void __launch_bounds__(TPB) knn_kernel(const void* __restrict__ uttsv) {
    __shared__ unsigned tbl[UTT_LEN * VOCAB];  // tbl[m*32+v]: bit q = (tok_q[m]==v)

    const unsigned tid   = threadIdx.x;
    const unsigned lane  = tid & 31;
    const unsigned warp  = tid >> 5;
    const unsigned chunk = blockIdx.x;
    const unsigned group = blockIdx.y;

    // Parallel table build: each of the 8 warps handles 2 positions.
    {
        const int is64 = g_u64;
        const unsigned col = group * 32 + lane;
        const long long* u64p = (const long long*)uttsv;
        const int*       u32p = (const int*)uttsv;
#pragma unroll
        for (int mm = 0; mm < 2; mm++) {
            int m = (int)(warp * 2 + mm);
            int tok = is64 ? (int)u64p[(size_t)m * BATCH + col]
                           : u32p[(size_t)m * BATCH + col];
#pragma unroll
            for (int v = 0; v < VOCAB; v++) {
                unsigned bm = __ballot_sync(0xffffffffu, tok == v);
                if (lane == (unsigned)v) tbl[m * VOCAB + v] = bm;
            }
        }
    }
    __syncthreads();

    const unsigned rowBase = chunk * CHUNK;
    const uint4* pk = reinterpret_cast<const uint4*>(g_packed) + rowBase + tid;
    const char* tbc = (const char*)tbl;

    unsigned mx0 = 0, mx1 = 0, mx2 = 0, mx3 = 0, mx4 = 0;
    unsigned b0 = 0, b1 = 0, b2 = 0, b3 = 0;

#define STEP(I)                                                                   \
    do {                                                                          \
        uint4 pw = pk[(I) * TPB];                                                 \
        unsigned l0  = *(const unsigned*)(tbc + 0 * 128  + __byte_perm(pw.x, 0, 0x4440)); \
        unsigned l1  = *(const unsigned*)(tbc + 1 * 128  + __byte_perm(pw.x, 0, 0x4441)); \
        unsigned l2  = *(const unsigned*)(tbc + 2 * 128  + __byte_perm(pw.x, 0, 0x4442)); \
        unsigned l3  = *(const unsigned*)(tbc + 3 * 128  + __byte_perm(pw.x, 0, 0x4443)); \
        unsigned l4  = *(const unsigned*)(tbc + 4 * 128  + __byte_perm(pw.y, 0, 0x4440)); \
        unsigned l5  = *(const unsigned*)(tbc + 5 * 128  + __byte_perm(pw.y, 0, 0x4441)); \
        unsigned l6  = *(const unsigned*)(tbc + 6 * 128  + __byte_perm(pw.y, 0, 0x4442)); \
        unsigned l7  = *(const unsigned*)(tbc + 7 * 128  + __byte_perm(pw.y, 0, 0x4443)); \
        unsigned l8  = *(const unsigned*)(tbc + 8 * 128  + __byte_perm(pw.z, 0, 0x4440)); \
        unsigned l9  = *(const unsigned*)(tbc + 9 * 128  + __byte_perm(pw.z, 0, 0x4441)); \
        unsigned l10 = *(const unsigned*)(tbc + 10 * 128 + __byte_perm(pw.z, 0, 0x4442)); \
        unsigned l11 = *(const unsigned*)(tbc + 11 * 128 + __byte_perm(pw.z, 0, 0x4443)); \
        unsigned l12 = *(const unsigned*)(tbc + 12 * 128 + __byte_perm(pw.w, 0, 0x4440)); \
        unsigned l13 = *(const unsigned*)(tbc + 13 * 128 + __byte_perm(pw.w, 0, 0x4441)); \
        unsigned l14 = *(const unsigned*)(tbc + 14 * 128 + __byte_perm(pw.w, 0, 0x4442)); \
        unsigned l15 = *(const unsigned*)(tbc + 15 * 128 + __byte_perm(pw.w, 0, 0x4443)); \
        unsigned s0, c0, s1, c1, s2, c2, s3, c3, s4, c4;                          \
        fa(l0, l1, l2, s0, c0);                                                   \
        fa(l3, l4, l5, s1, c1);                                                   \
        fa(l6, l7, l8, s2, c2);                                                   \
        fa(l9, l10, l11, s3, c3);                                                 \
        fa(l12, l13, l14, s4, c4);                                                \
        unsigned t0, d0, t1, d1;                                                  \
        fa(s0, s1, s2, t0, d0);                                                   \
        fa(s3, s4, l15, t1, d1);                                                  \
        unsigned n0, e0; ha(t0, t1, n0, e0);                                      \
        unsigned f0, g0, f1, g1, f2, g2;                                          \
        fa(c0, c1, c2, f0, g0);                                                   \
        fa(c3, c4, d0, f1, g1);                                                   \
        fa(f0, f1, d1, f2, g2);                                                   \
        unsigned n1, g3; ha(f2, e0, n1, g3);                                      \
        unsigned h0, k0; fa(g0, g1, g2, h0, k0);                                  \
        unsigned n2, k1; ha(h0, g3, n2, k1);                                      \
        unsigned n3, n4; ha(k0, k1, n3, n4);                                      \
        unsigned gt = n0 & ~mx0;                                                  \
        gt = (n1 & ~mx1) | (~(n1 ^ mx1) & gt);                                    \
        gt = (n2 & ~mx2) | (~(n2 ^ mx2) & gt);                                    \
        gt = (n3 & ~mx3) | (~(n3 ^ mx3) & gt);                                    \
        gt = (n4 & ~mx4) | (~(n4 ^ mx4) & gt);                                    \
        mx0 = (n0 & gt) | (mx0 & ~gt);                                            \
        mx1 = (n1 & gt) | (mx1 & ~gt);                                            \
        mx2 = (n2 & gt) | (mx2 & ~gt);                                            \
        mx3 = (n3 & gt) | (mx3 & ~gt);                                            \
        mx4 = (n4 & gt) | (mx4 & ~gt);                                            \
        if ((I) & 1)  b0 |= gt; else b0 &= ~gt;                                   \
        if ((I) & 2)  b1 |= gt; else b1 &= ~gt;                                   \
        if ((I) & 4)  b2 |= gt; else b2 &= ~gt;                                   \
        if ((I) & 8)  b3 |= gt; else b3 &= ~gt;                                   \
    } while (0)

    STEP(0);  STEP(1);  STEP(2);  STEP(3);  STEP(4);  STEP(5);
    STEP(6);  STEP(7);  STEP(8);  STEP(9);  STEP(10); STEP(11);
    if (tid < TAIL) STEP(12);
#undef STEP

    // Materialize full row planes: row = tid (8 bits) | iter (4 bits).
    unsigned mx[5] = {mx0, mx1, mx2, mx3, mx4};
    unsigned bi[12];
#pragma unroll
    for (int p = 0; p < 8; p++) bi[p] = (tid & (1u << p)) ? 0xffffffffu : 0u;
    bi[8] = b0; bi[9] = b1; bi[10] = b2; bi[11] = b3;

    // Warp butterfly merge of (cnt desc, row asc), bit-sliced.
#pragma unroll
    for (int k = 1; k < 32; k <<= 1) {
        unsigned o[5], q[12];
#pragma unroll
        for (int p = 0; p < 5; p++)  o[p] = __shfl_xor_sync(0xffffffffu, mx[p], k);
#pragma unroll
        for (int p = 0; p < 12; p++) q[p] = __shfl_xor_sync(0xffffffffu, bi[p], k);
        unsigned gtc = mx[0] & ~o[0];
#pragma unroll
        for (int p = 1; p < 5; p++)
            gtc = (mx[p] & ~o[p]) | (~(mx[p] ^ o[p]) & gtc);
        unsigned orx = 0;
#pragma unroll
        for (int p = 0; p < 5; p++) orx |= mx[p] ^ o[p];    // ~orx = counts equal
        unsigned lt = ~bi[0] & q[0];
#pragma unroll
        for (int p = 1; p < 12; p++)
            lt = (~bi[p] & q[p]) | (~(bi[p] ^ q[p]) & lt);  // my row < partner row
        unsigned tm = gtc | (lt & ~orx);                    // keep mine
#pragma unroll
        for (int p = 0; p < 5; p++)  mx[p] = (mx[p] & tm) | (o[p] & ~tm);
#pragma unroll
        for (int p = 0; p < 12; p++) bi[p] = (bi[p] & tm) | (q[p] & ~tm);
    }

    // lane q extracts query q's (cnt,row) from the merged planes
    unsigned cnt = 0, lr = 0;
#pragma unroll
    for (int p = 0; p < 5; p++)  cnt |= ((mx[p] >> lane) & 1u) << p;
#pragma unroll
    for (int p = 0; p < 12; p++) lr  |= ((bi[p] >> lane) & 1u) << p;
    unsigned row = rowBase + lr;                 // lr = tid + iter*256
    unsigned key = (cnt << 17) | (131071u - row);
    atomicMax(&g_keys[group * 32 + lane], key);
}

// ---------------------------------------------------------------------------
// Kernel 3: gather meanings of the winner and emit one-hot output.
// ---------------------------------------------------------------------------
__global__ void out_kernel(const void* __restrict__ meanv, float* __restrict__ out) {
    int idx = blockIdx.x * blockDim.x + threadIdx.x;
    if (idx >= BATCH * NTYPES * MPT) return;
    int n = idx / (NTYPES * MPT);
    int r = idx % (NTYPES * MPT);
    int t = r / MPT;
    int c = r % MPT;
    unsigned key = __ldg(&g_keys[n]);
    int row = 131071 - (int)(key & 0x1FFFFu);
    long long mval = g_m64 ? __ldg((const long long*)meanv + (size_t)row * NTYPES + t)
                           : (long long)__ldg((const int*)meanv + (size_t)row * NTYPES + t);
    out[idx] = (mval == (long long)c) ? 1.0f : 0.0f;
}

extern "C" void kernel_launch(void* const* d_in, const int* in_sizes, int n_in,
                              void* d_out, int out_size) {
    const void*  utts     = d_in[0];                 // [16,2048] int64/int32
    const float* support  = (const float*)d_in[1];   // [100000,512] fp32 one-hot
    const void*  meanings = (const void*)d_in[2];    // [100000,5] int64/int32
    float* out = (float*)d_out;                      // [2048,5,10] fp32

    // one warp per 32 entries: 1.6M entries -> 50000 warps -> 6250 blocks
    decode_kernel<<<(ENTRIES / 32 + 7) / 8, 256>>>(
        support, (const int*)utts, (const int*)meanings);
    dim3 grid(NS, NGROUPS);
    knn_kernel<<<grid, TPB>>>(utts);
    out_kernel<<<(BATCH * NTYPES * MPT + 127) / 128, 128>>>(meanings, out);
}

// round 9
// speedup vs baseline: 1.0534x; 1.0534x over previous
#include <cuda_runtime.h>

#define VOCAB 32
#define UTT_LEN 16
#define NTYPES 5
#define MPT 10
#define SUPPORT 100000
#define BATCH 2048

#define NS 16                            // support chunks
#define CHUNK (SUPPORT / NS)             // 6250
#define TPB 128                          // 4-warp blocks: whole grid co-resident
#define FULL_ITERS (CHUNK / TPB)         // 48
#define TAIL (CHUNK - FULL_ITERS * TPB)  // 106
#define NGROUPS (BATCH / 32)             // 64

#define ENTRIES (SUPPORT * UTT_LEN)      // 1,600,000 (divisible by 32)

// scratch (no cudaMalloc allowed)
__device__ unsigned char g_packed[ENTRIES];           // token*4 per position
__device__ unsigned int  g_keys[BATCH];               // (cnt<<17)|(131071-row)
__device__ int g_u64, g_m64;                          // dtype flags

// ---------------------------------------------------------------------------
// Kernel 1 (fused): detect int width + zero keys + decode one-hot support.
// R3-exact (33.8us, DRAM 78% ~ achievable wall for the compulsory 204.8MB).
// ---------------------------------------------------------------------------
__global__ void __launch_bounds__(256) decode_kernel(
        const float* __restrict__ support,
        const int* __restrict__ utts32,
        const int* __restrict__ mean32) {
    const unsigned tid  = blockIdx.x * blockDim.x + threadIdx.x;
    const unsigned lane = threadIdx.x & 31;

    // fused dtype detection (first warp). Values are small non-negative ints;
    // if int64 (LE), every odd 32-bit word of the first 128 pairs is 0.
    if (tid < 32) {
        bool unz = false, mnz = false;
        for (int i = (int)tid; i < 128; i += 32) {
            unz |= (utts32[2 * i + 1] != 0);
            mnz |= (mean32[2 * i + 1] != 0);
        }
        unsigned ub = __ballot_sync(0xffffffffu, unz);
        unsigned mb = __ballot_sync(0xffffffffu, mnz);
        if (tid == 0) { g_u64 = (ub == 0); g_m64 = (mb == 0); }
    }
    if (tid < BATCH) g_keys[tid] = 0u;

    const unsigned gwarp = tid >> 5;              // global warp id
    const unsigned base  = gwarp * 32;            // first entry of this warp
    if (base >= ENTRIES) return;

    const float4* p = reinterpret_cast<const float4*>(support) + (size_t)base * 8;
    const int myr = (int)(lane >> 2);             // round holding my entry
    const int sh  = (int)(lane & 3) * 8;          // byte of my entry in ballots

    unsigned mysub = 0;
#pragma unroll
    for (int r = 0; r < 8; r++) {
        float4 v = __ldcs(p + r * 32 + lane);     // 512B contiguous, streaming
        unsigned bx = __ballot_sync(0xffffffffu, v.x != 0.0f);
        unsigned by = __ballot_sync(0xffffffffu, v.y != 0.0f);
        unsigned bz = __ballot_sync(0xffffffffu, v.z != 0.0f);
        unsigned bw = __ballot_sync(0xffffffffu, v.w != 0.0f);
        unsigned sub = ((bx >> sh) & 0xFFu)
                     | (((by >> sh) & 0xFFu) << 8)
                     | (((bz >> sh) & 0xFFu) << 16)
                     | (((bw >> sh) & 0xFFu) << 24);
        if (r == myr) mysub = sub;
    }
    int b = __ffs(mysub) - 1;                     // bit index in submask
    int v = ((b & 7) << 2) | (b >> 3);            // vocab token
    g_packed[base + lane] = (unsigned char)(v << 2);  // pre-scaled x4
}

// ---------------------------------------------------------------------------
// Kernel 2: bit-sliced match counting + argmax. Same math as R3; block shape
// 128 threads so all 1024 blocks are co-resident (single wave, no tail idle)
// and the per-block merge epilogue total is halved. Mainloop: 12 x 4 STEPs;
// iter bits 0-1 static per STEP, bits 2-5 via per-j runtime masks.
// ---------------------------------------------------------------------------
__device__ __forceinline__ void fa(unsigned a, unsigned b, unsigned c,
                                   unsigned& s, unsigned& cy) {
    s  = a ^ b ^ c;                       // LOP3 0x96
    cy = (a & b) | (a & c) | (b & c);     // LOP3 0xE8
}
__device__ __forceinline__ void ha(unsigned a, unsigned b,
                                   unsigned& s, unsigned& cy) {
    s = a ^ b; cy = a & b;
}

__global__ void __launch_bounds__(TPB) knn_kernel(const void* __restrict__ uttsv) {
    __shared__ unsigned tbl[UTT_LEN * VOCAB];  // tbl[m*32+v]: bit q = (tok_q[m]==v)

    const unsigned tid   = threadIdx.x;        // 0..127
    const unsigned lane  = tid & 31;
    const unsigned warp  = tid >> 5;           // 0..3
    const unsigned chunk = blockIdx.x;
    const unsigned group = blockIdx.y;

    // Parallel table build: each of the 4 warps handles 4 positions.
    {
        const int is64 = g_u64;
        const unsigned col = group * 32 + lane;
        const long long* u64p = (const long long*)uttsv;
        const int*       u32p = (const int*)uttsv;
#pragma unroll
        for (int mm = 0; mm < 4; mm++) {
            int m = (int)(warp * 4 + mm);
            int tok = is64 ? (int)u64p[(size_t)m * BATCH + col]
                           : u32p[(size_t)m * BATCH + col];
#pragma unroll
            for (int v = 0; v < VOCAB; v++) {
                unsigned bm = __ballot_sync(0xffffffffu, tok == v);
                if (lane == (unsigned)v) tbl[m * VOCAB + v] = bm;
            }
        }
    }
    __syncthreads();

    const unsigned rowBase = chunk * CHUNK;
    const uint4* pk = reinterpret_cast<const uint4*>(g_packed) + rowBase + tid;
    const char* tbc = (const char*)tbl;

    unsigned mx0 = 0, mx1 = 0, mx2 = 0, mx3 = 0, mx4 = 0;
    unsigned b0 = 0, b1 = 0, b2 = 0, b3 = 0, b4 = 0, b5 = 0;

// STEP with static low iter bits (K = 0..3) and runtime masks jm0..jm3 for
// iter bits 2..5. I = 4*j + K.
#define STEP(K, IDX)                                                              \
    do {                                                                          \
        uint4 pw = pk[(IDX) * TPB];                                               \
        unsigned l0  = *(const unsigned*)(tbc + 0 * 128  + __byte_perm(pw.x, 0, 0x4440)); \
        unsigned l1  = *(const unsigned*)(tbc + 1 * 128  + __byte_perm(pw.x, 0, 0x4441)); \
        unsigned l2  = *(const unsigned*)(tbc + 2 * 128  + __byte_perm(pw.x, 0, 0x4442)); \
        unsigned l3  = *(const unsigned*)(tbc + 3 * 128  + __byte_perm(pw.x, 0, 0x4443)); \
        unsigned l4  = *(const unsigned*)(tbc + 4 * 128  + __byte_perm(pw.y, 0, 0x4440)); \
        unsigned l5  = *(const unsigned*)(tbc + 5 * 128  + __byte_perm(pw.y, 0, 0x4441)); \
        unsigned l6  = *(const unsigned*)(tbc + 6 * 128  + __byte_perm(pw.y, 0, 0x4442)); \
        unsigned l7  = *(const unsigned*)(tbc + 7 * 128  + __byte_perm(pw.y, 0, 0x4443)); \
        unsigned l8  = *(const unsigned*)(tbc + 8 * 128  + __byte_perm(pw.z, 0, 0x4440)); \
        unsigned l9  = *(const unsigned*)(tbc + 9 * 128  + __byte_perm(pw.z, 0, 0x4441)); \
        unsigned l10 = *(const unsigned*)(tbc + 10 * 128 + __byte_perm(pw.z, 0, 0x4442)); \
        unsigned l11 = *(const unsigned*)(tbc + 11 * 128 + __byte_perm(pw.z, 0, 0x4443)); \
        unsigned l12 = *(const unsigned*)(tbc + 12 * 128 + __byte_perm(pw.w, 0, 0x4440)); \
        unsigned l13 = *(const unsigned*)(tbc + 13 * 128 + __byte_perm(pw.w, 0, 0x4441)); \
        unsigned l14 = *(const unsigned*)(tbc + 14 * 128 + __byte_perm(pw.w, 0, 0x4442)); \
        unsigned l15 = *(const unsigned*)(tbc + 15 * 128 + __byte_perm(pw.w, 0, 0x4443)); \
        unsigned s0, c0, s1, c1, s2, c2, s3, c3, s4, c4;                          \
        fa(l0, l1, l2, s0, c0);                                                   \
        fa(l3, l4, l5, s1, c1);                                                   \
        fa(l6, l7, l8, s2, c2);                                                   \
        fa(l9, l10, l11, s3, c3);                                                 \
        fa(l12, l13, l14, s4, c4);                                                \
        unsigned t0, d0, t1, d1;                                                  \
        fa(s0, s1, s2, t0, d0);                                                   \
        fa(s3, s4, l15, t1, d1);                                                  \
        unsigned n0, e0; ha(t0, t1, n0, e0);                                      \
        unsigned f0, g0, f1, g1, f2, g2;                                          \
        fa(c0, c1, c2, f0, g0);                                                   \
        fa(c3, c4, d0, f1, g1);                                                   \
        fa(f0, f1, d1, f2, g2);                                                   \
        unsigned n1, g3; ha(f2, e0, n1, g3);                                      \
        unsigned h0, k0; fa(g0, g1, g2, h0, k0);                                  \
        unsigned n2, k1; ha(h0, g3, n2, k1);                                      \
        unsigned n3, n4; ha(k0, k1, n3, n4);                                      \
        unsigned gt = n0 & ~mx0;                                                  \
        gt = (n1 & ~mx1) | (~(n1 ^ mx1) & gt);                                    \
        gt = (n2 & ~mx2) | (~(n2 ^ mx2) & gt);                                    \
        gt = (n3 & ~mx3) | (~(n3 ^ mx3) & gt);                                    \
        gt = (n4 & ~mx4) | (~(n4 ^ mx4) & gt);                                    \
        mx0 = (n0 & gt) | (mx0 & ~gt);                                            \
        mx1 = (n1 & gt) | (mx1 & ~gt);                                            \
        mx2 = (n2 & gt) | (mx2 & ~gt);                                            \
        mx3 = (n3 & gt) | (mx3 & ~gt);                                            \
        mx4 = (n4 & gt) | (mx4 & ~gt);                                            \
        if ((K) & 1) b0 |= gt; else b0 &= ~gt;                                    \
        if ((K) & 2) b1 |= gt; else b1 &= ~gt;                                    \
        b2 = (jm0 & gt) | (b2 & ~gt);                                             \
        b3 = (jm1 & gt) | (b3 & ~gt);                                             \
        b4 = (jm2 & gt) | (b4 & ~gt);                                             \
        b5 = (jm3 & gt) | (b5 & ~gt);                                             \
    } while (0)

#pragma unroll 2
    for (int j = 0; j < 12; j++) {
        const unsigned jm0 = (unsigned)(-(int)((j >> 0) & 1));
        const unsigned jm1 = (unsigned)(-(int)((j >> 1) & 1));
        const unsigned jm2 = (unsigned)(-(int)((j >> 2) & 1));
        const unsigned jm3 = (unsigned)(-(int)((j >> 3) & 1));
        STEP(0, j * 4 + 0);
        STEP(1, j * 4 + 1);
        STEP(2, j * 4 + 2);
        STEP(3, j * 4 + 3);
    }
    // tail: I = 48 (j=12, k=0): iter bits -> b4,b5 set; b2,b3 clear
    if (tid < TAIL) {
        const unsigned jm0 = 0u, jm1 = 0u, jm2 = 0xffffffffu, jm3 = 0xffffffffu;
        STEP(0, 48);
    }
#undef STEP

    // Materialize full row planes: row = tid (7 bits) | iter (6 bits).
    unsigned mx[5] = {mx0, mx1, mx2, mx3, mx4};
    unsigned bi[13];
#pragma unroll
    for (int p = 0; p < 7; p++) bi[p] = (tid & (1u << p)) ? 0xffffffffu : 0u;
    bi[7] = b0; bi[8] = b1; bi[9] = b2; bi[10] = b3; bi[11] = b4; bi[12] = b5;

    // Warp butterfly merge of (cnt desc, row asc), bit-sliced.
#pragma unroll
    for (int k = 1; k < 32; k <<= 1) {
        unsigned o[5], q[13];
#pragma unroll
        for (int p = 0; p < 5; p++)  o[p] = __shfl_xor_sync(0xffffffffu, mx[p], k);
#pragma unroll
        for (int p = 0; p < 13; p++) q[p] = __shfl_xor_sync(0xffffffffu, bi[p], k);
        unsigned gtc = mx[0] & ~o[0];
#pragma unroll
        for (int p = 1; p < 5; p++)
            gtc = (mx[p] & ~o[p]) | (~(mx[p] ^ o[p]) & gtc);
        unsigned orx = 0;
#pragma unroll
        for (int p = 0; p < 5; p++) orx |= mx[p] ^ o[p];    // ~orx = counts equal
        unsigned lt = ~bi[0] & q[0];
#pragma unroll
        for (int p = 1; p < 13; p++)
            lt = (~bi[p] & q[p]) | (~(bi[p] ^ q[p]) & lt);  // my row < partner row
        unsigned tm = gtc | (lt & ~orx);                    // keep mine
#pragma unroll
        for (int p = 0; p < 5; p++)  mx[p] = (mx[p] & tm) | (o[p] & ~tm);
#pragma unroll
        for (int p = 0; p < 13; p++) bi[p] = (bi[p] & tm) | (q[p] & ~tm);
    }

    // lane q extracts query q's (cnt,row) from the merged planes
    unsigned cnt = 0, lr = 0;
#pragma unroll
    for (int p = 0; p < 5; p++)  cnt |= ((mx[p] >> lane) & 1u) << p;
#pragma unroll
    for (int p = 0; p < 13; p++) lr  |= ((bi[p] >> lane) & 1u) << p;
    unsigned row = rowBase + lr;                 // lr = tid + iter*128
    unsigned key = (cnt << 17) | (131071u - row);
    atomicMax(&g_keys[group * 32 + lane], key);
}

// ---------------------------------------------------------------------------
// Kernel 3: one thread per query: 1 key load, 5 meaning loads, 25 float2
// stores (200B contiguous per query, 8B aligned).
// ---------------------------------------------------------------------------
__global__ void __launch_bounds__(128) out_kernel(const void* __restrict__ meanv,
                                                  float* __restrict__ out) {
    const int q = blockIdx.x * blockDim.x + threadIdx.x;   // 0..2047
    if (q >= BATCH) return;
    const int m64 = g_m64;
    unsigned key = __ldg(&g_keys[q]);
    int row = 131071 - (int)(key & 0x1FFFFu);

    int m[NTYPES];
#pragma unroll
    for (int t = 0; t < NTYPES; t++)
        m[t] = m64 ? (int)__ldg((const long long*)meanv + (size_t)row * NTYPES + t)
                   : __ldg((const int*)meanv + (size_t)row * NTYPES + t);

    float2* o = reinterpret_cast<float2*>(out + (size_t)q * NTYPES * MPT);
#pragma unroll
    for (int e = 0; e < (NTYPES * MPT) / 2; e++) {
        const int e0 = 2 * e, e1 = 2 * e + 1;
        float2 v;
        v.x = (m[e0 / MPT] == e0 % MPT) ? 1.0f : 0.0f;
        v.y = (m[e1 / MPT] == e1 % MPT) ? 1.0f : 0.0f;
        o[e] = v;
    }
}

extern "C" void kernel_launch(void* const* d_in, const int* in_sizes, int n_in,
                              void* d_out, int out_size) {
    const void*  utts     = d_in[0];                 // [16,2048] int64/int32
    const float* support  = (const float*)d_in[1];   // [100000,512] fp32 one-hot
    const void*  meanings = (const void*)d_in[2];    // [100000,5] int64/int32
    float* out = (float*)d_out;                      // [2048,5,10] fp32

    // one warp per 32 entries: 1.6M entries -> 50000 warps -> 6250 blocks
    decode_kernel<<<(ENTRIES / 32 + 7) / 8, 256>>>(
        support, (const int*)utts, (const int*)meanings);
    dim3 grid(NS, NGROUPS);                          // (16,64) = 1024 blocks
    knn_kernel<<<grid, TPB>>>(utts);
    out_kernel<<<(BATCH + 127) / 128, 128>>>(meanings, out);
}